// round 7
// baseline (speedup 1.0000x reference)
#include <cuda_runtime.h>
#include <cuda_bf16.h>
#include <math.h>

#define Bsz  512
#define NTOK 20
#define Dm   128
#define Hh   8
#define FFd  512
#define HIDd 512

// padded qkv layout inside k_mha: idx = t*137 + h*17 + kd  (max 2737)
#define QIDX(t,h,k) ((t)*137 + (h)*17 + (k))

// ---------------- device scratch (no cudaMalloc allowed) ----------------
__device__ float g_x[Bsz*NTOK*Dm];       // compacted embeddings (encoder input)
__device__ float g_crd[Bsz*NTOK*2];      // compacted coords
__device__ int   g_nidx[Bsz*NTOK];       // compacted node indices
__device__ float g_buf1[Bsz*NTOK*Dm];    // post-MHA residual (pre-bn1)
__device__ float g_buf2[Bsz*NTOK*Dm];    // post-FFN residual (pre-bn2)
__device__ float g_psum[Bsz*Dm];
__device__ float g_psq[Bsz*Dm];
__device__ float g_bn1s[Dm], g_bn1h[Dm], g_bn2s[Dm], g_bn2h[Dm];
__device__ float g_ctxq[Dm];             // (W_ph @ W_step), batch-independent
__device__ float g_cph[HIDd];            // bc1 + W_ph @ Wc1[128:384,:]
__device__ float g_prev[Bsz*2];
__device__ float g_first[Bsz*2];
__device__ int   g_tours[Bsz*NTOK];

// ---------------- x = coords@Wi + bi ; init crd / node_idx ----------------
__global__ void k_embed(const float* __restrict__ coords,
                        const float* __restrict__ Wi,
                        const float* __restrict__ bi)
{
    int b = blockIdx.x, tid = threadIdx.x;
    float w0 = Wi[tid], w1 = Wi[Dm + tid], bb = bi[tid];
    const float* cb = coords + b*NTOK*2;
    float* xb = g_x + (size_t)b*NTOK*Dm;
    #pragma unroll
    for (int t = 0; t < NTOK; t++)
        xb[t*Dm + tid] = cb[2*t]*w0 + cb[2*t+1]*w1 + bb;
    if (tid < NTOK*2) g_crd[b*NTOK*2 + tid] = cb[tid];
    if (tid < NTOK)   g_nidx[b*NTOK + tid] = tid;
}

// ---------------- constants: ctx_q and value-head placeholder term ----------------
__global__ void k_setup(const float* __restrict__ W_ph, const float* __restrict__ W_step,
                        const float* __restrict__ Wc1,  const float* __restrict__ bc1)
{
    __shared__ float ph[2*Dm];
    int tid = threadIdx.x;                 // 512 threads
    if (tid < 2*Dm) ph[tid] = W_ph[tid];
    __syncthreads();
    if (tid < Dm) {
        float a = 0.f;
        for (int k = 0; k < 2*Dm; k++) a += ph[k]*W_step[k*Dm + tid];
        g_ctxq[tid] = a;
    }
    float c = bc1[tid];
    for (int k = 0; k < 2*Dm; k++) c += ph[k]*Wc1[(Dm + k)*HIDd + tid];
    g_cph[tid] = c;
}

// ---------------- MHA + residual + BN partial sums ----------------
// src==0: input = g_x (raw). src==1: input = bn2(g_buf2).
__global__ void __launch_bounds__(128) k_mha(int src,
        const float* __restrict__ Wq, const float* __restrict__ Wk,
        const float* __restrict__ Wv, const float* __restrict__ Wo, int n)
{
    __shared__ float xs[NTOK][Dm];
    __shared__ float qs[2740];
    __shared__ float ks2[2740];
    __shared__ float vs[2740];
    int b = blockIdx.x, tid = threadIdx.x;
    const float* xin = (src ? g_buf2 : g_x) + (size_t)b*NTOK*Dm;
    float sc = src ? g_bn2s[tid] : 1.f;
    float sh = src ? g_bn2h[tid] : 0.f;
    #pragma unroll
    for (int t = 0; t < NTOK; t++)
        xs[t][tid] = (t < n) ? (xin[t*Dm + tid]*sc + sh) : 0.f;
    __syncthreads();

    int h = tid >> 4, kd = tid & 15;
    // fused q,k,v projections, 10-token chunks
    const float* wq = Wq + h*2048 + kd;
    const float* wk = Wk + h*2048 + kd;
    const float* wv = Wv + h*2048 + kd;
    for (int t0 = 0; t0 < n; t0 += 10) {
        float aq[10], ak[10], av[10];
        #pragma unroll
        for (int u = 0; u < 10; u++) { aq[u]=0.f; ak[u]=0.f; av[u]=0.f; }
        for (int d = 0; d < Dm; d++) {
            float wqv = wq[d*16], wkv = wk[d*16], wvv = wv[d*16];
            #pragma unroll
            for (int u = 0; u < 10; u++) {
                float xv = xs[t0+u][d];
                aq[u] += xv*wqv; ak[u] += xv*wkv; av[u] += xv*wvv;
            }
        }
        #pragma unroll
        for (int u = 0; u < 10; u++) {
            int t = t0 + u;
            qs[QIDX(t,h,kd)] = aq[u];
            ks2[QIDX(t,h,kd)] = ak[u];
            vs[QIDX(t,h,kd)] = av[u];
        }
    }
    __syncthreads();

    // attention: one (t,h) pair per thread, up to 2 iterations (n*8 <= 160)
    int npairs = n * Hh;
    float outr[2][16];
    #pragma unroll
    for (int it = 0; it < 2; it++) {
        int pair = tid + it*128;
        if (pair < npairs) {
            int t = pair >> 3, hh = pair & 7;
            float qreg[16];
            #pragma unroll
            for (int j = 0; j < 16; j++) qreg[j] = qs[QIDX(t,hh,j)];
            float s[NTOK];
            float mx = -1e30f;
            #pragma unroll
            for (int m = 0; m < NTOK; m++) if (m < n) {
                float p = 0.f;
                #pragma unroll
                for (int j = 0; j < 16; j++) p += qreg[j]*ks2[QIDX(m,hh,j)];
                p *= 0.25f;
                s[m] = p;
                mx = fmaxf(mx, p);
            }
            float ssum = 0.f;
            #pragma unroll
            for (int m = 0; m < NTOK; m++) if (m < n) {
                float e = expf(s[m]-mx); s[m] = e; ssum += e;
            }
            float inv = 1.f/ssum;
            float o[16];
            #pragma unroll
            for (int j = 0; j < 16; j++) o[j] = 0.f;
            #pragma unroll
            for (int m = 0; m < NTOK; m++) if (m < n) {
                float a = s[m]*inv;
                #pragma unroll
                for (int j = 0; j < 16; j++) o[j] += a*vs[QIDX(m,hh,j)];
            }
            #pragma unroll
            for (int j = 0; j < 16; j++) outr[it][j] = o[j];
        }
    }
    __syncthreads();
    // write attention output into qs (reuse)
    #pragma unroll
    for (int it = 0; it < 2; it++) {
        int pair = tid + it*128;
        if (pair < npairs) {
            int t = pair >> 3, hh = pair & 7;
            #pragma unroll
            for (int j = 0; j < 16; j++) qs[QIDX(t,hh,j)] = outr[it][j];
        }
    }
    __syncthreads();

    // output projection + residual + BN partials (thread = feature d)
    float psum = 0.f, psq = 0.f;
    for (int t0 = 0; t0 < n; t0 += 10) {
        float acc[10];
        #pragma unroll
        for (int u = 0; u < 10; u++) acc[u] = 0.f;
        for (int j = 0; j < Dm; j++) {
            float w = Wo[j*Dm + tid];
            int off = (j >> 4)*17 + (j & 15);
            #pragma unroll
            for (int u = 0; u < 10; u++) acc[u] += qs[(t0+u)*137 + off]*w;
        }
        #pragma unroll
        for (int u = 0; u < 10; u++) {
            int t = t0 + u;
            if (t < n) {
                float y = xs[t][tid] + acc[u];
                g_buf1[(size_t)b*NTOK*Dm + t*Dm + tid] = y;
                psum += y; psq += y*y;
            }
        }
    }
    g_psum[b*Dm + tid] = psum;
    g_psq[b*Dm + tid] = psq;
}

// ---------------- BN stats reduce: deterministic tree, double accum ----------------
__global__ void k_bnred(int which, const float* __restrict__ gam,
                        const float* __restrict__ bet, int n)
{
    int d = blockIdx.x, tid = threadIdx.x;   // 128 blocks x 128 threads
    double s = 0.0, sq = 0.0;
    for (int j = tid; j < Bsz; j += 128) {
        s  += (double)g_psum[j*Dm + d];
        sq += (double)g_psq[j*Dm + d];
    }
    __shared__ double rs[128], rq[128];
    rs[tid] = s; rq[tid] = sq;
    __syncthreads();
    for (int st = 64; st > 0; st >>= 1) {
        if (tid < st) { rs[tid] += rs[tid+st]; rq[tid] += rq[tid+st]; }
        __syncthreads();
    }
    if (tid == 0) {
        double cnt = (double)Bsz * (double)n;
        double m = rs[0]/cnt;
        double v = rq[0]/cnt - m*m;
        float scl = gam[d] / sqrtf((float)v + 1e-5f);
        float hh  = bet[d] - (float)m*scl;
        if (which == 1) { g_bn1s[d] = scl; g_bn1h[d] = hh; }
        else            { g_bn2s[d] = scl; g_bn2h[d] = hh; }
    }
}

// ---------------- FFN + residual + BN partials (input = bn1(g_buf1)) ----------------
__global__ void __launch_bounds__(128) k_ffn(
        const float* __restrict__ W1, const float* __restrict__ b1,
        const float* __restrict__ W2, const float* __restrict__ b2, int n)
{
    __shared__ float us[NTOK][Dm];
    __shared__ float f1s[10][516];
    int b = blockIdx.x, tid = threadIdx.x;
    float s1 = g_bn1s[tid], h1 = g_bn1h[tid];
    #pragma unroll
    for (int t = 0; t < NTOK; t++)
        us[t][tid] = (t < n) ? (g_buf1[(size_t)b*NTOK*Dm + t*Dm + tid]*s1 + h1) : 0.f;
    float bv0 = b1[tid], bv1 = b1[128+tid], bv2 = b1[256+tid], bv3 = b1[384+tid];
    float b2v = b2[tid];
    float psum = 0.f, psq = 0.f;
    __syncthreads();
    for (int t0 = 0; t0 < n; t0 += 10) {
        // stage 1: f1 = relu(u@W1 + b1), thread covers hidden j = tid + 128r
        float a0[10], a1[10], a2[10], a3[10];
        #pragma unroll
        for (int u = 0; u < 10; u++) { a0[u]=bv0; a1[u]=bv1; a2[u]=bv2; a3[u]=bv3; }
        for (int d = 0; d < Dm; d++) {
            const float* wr = W1 + d*FFd + tid;
            float w0 = wr[0], w1 = wr[128], w2 = wr[256], w3 = wr[384];
            #pragma unroll
            for (int u = 0; u < 10; u++) {
                float xv = us[t0+u][d];
                a0[u] += xv*w0; a1[u] += xv*w1; a2[u] += xv*w2; a3[u] += xv*w3;
            }
        }
        #pragma unroll
        for (int u = 0; u < 10; u++) {
            f1s[u][tid      ] = fmaxf(a0[u], 0.f);
            f1s[u][tid + 128] = fmaxf(a1[u], 0.f);
            f1s[u][tid + 256] = fmaxf(a2[u], 0.f);
            f1s[u][tid + 384] = fmaxf(a3[u], 0.f);
        }
        __syncthreads();
        // stage 2: f2 = f1@W2 + b2, thread = feature d
        float c[10];
        #pragma unroll
        for (int u = 0; u < 10; u++) c[u] = b2v;
        for (int j = 0; j < FFd; j++) {
            float w = W2[j*Dm + tid];
            #pragma unroll
            for (int u = 0; u < 10; u++) c[u] += f1s[u][j]*w;
        }
        #pragma unroll
        for (int u = 0; u < 10; u++) {
            int t = t0 + u;
            if (t < n) {
                float y = us[t][tid] + c[u];
                g_buf2[(size_t)b*NTOK*Dm + t*Dm + tid] = y;
                psum += y; psq += y*y;
            }
        }
        __syncthreads();
    }
    g_psum[b*Dm + tid] = psum;
    g_psq[b*Dm + tid] = psq;
}

// ---------------- decode step: glimpse attention, logits, argmax, outputs, compaction ----------------
__global__ void __launch_bounds__(128) k_decode(int i, int n,
        const float* __restrict__ W_node, const float* __restrict__ W_fixed,
        const float* __restrict__ W_out,  const float* __restrict__ Wc1,
        const float* __restrict__ Wc2,    const float* __restrict__ bc2,
        float* __restrict__ out)
{
    __shared__ float es[NTOK][Dm];
    __shared__ float ps[NTOK*384];   // gK | gV | lK per token
    __shared__ float gms[Dm], qv[Dm], glim[Dm], go[Dm];
    __shared__ float logit_s[NTOK];
    __shared__ float red[128];
    __shared__ int   sel_s;
    __shared__ float lp_s;
    int b = blockIdx.x, tid = threadIdx.x;

    // E = bn2(buf2); g_mean
    float s2 = g_bn2s[tid], h2 = g_bn2h[tid];
    float gsum = 0.f;
    #pragma unroll
    for (int t = 0; t < NTOK; t++) {
        float e = (t < n) ? (g_buf2[(size_t)b*NTOK*Dm + t*Dm + tid]*s2 + h2) : 0.f;
        es[t][tid] = e; gsum += e;
    }
    gms[tid] = gsum / (float)n;
    __syncthreads();

    // q = g_mean @ W_fixed + ctx_q
    float qa = g_ctxq[tid];
    for (int k = 0; k < Dm; k++) qa += gms[k]*W_fixed[k*Dm + tid];
    qv[tid] = qa;

    // P = E @ W_node  (n x 384), thread covers cols tid, tid+128, tid+256
    for (int t0 = 0; t0 < n; t0 += 10) {
        float a0[10], a1[10], a2[10];
        #pragma unroll
        for (int u = 0; u < 10; u++) { a0[u]=0.f; a1[u]=0.f; a2[u]=0.f; }
        for (int d = 0; d < Dm; d++) {
            const float* wr = W_node + d*384 + tid;
            float w0 = wr[0], w1 = wr[128], w2 = wr[256];
            #pragma unroll
            for (int u = 0; u < 10; u++) {
                float xv = es[t0+u][d];
                a0[u] += xv*w0; a1[u] += xv*w1; a2[u] += xv*w2;
            }
        }
        #pragma unroll
        for (int u = 0; u < 10; u++) {
            int t = t0 + u;
            ps[t*384 + tid      ] = a0[u];
            ps[t*384 + tid + 128] = a1[u];
            ps[t*384 + tid + 256] = a2[u];
        }
    }
    __syncthreads();

    // glimpse attention: thread tid = (h, kd) with tid == h*16+kd
    {
        float qh = qv[tid];
        float sc[NTOK];
        float mx = -1e30f;
        #pragma unroll
        for (int m = 0; m < NTOK; m++) if (m < n) {
            float p = qh * ps[m*384 + tid];
            #pragma unroll
            for (int o = 8; o > 0; o >>= 1) p += __shfl_xor_sync(0xffffffffu, p, o, 16);
            p *= 0.25f;
            sc[m] = p;
            mx = fmaxf(mx, p);
        }
        float ssum = 0.f;
        #pragma unroll
        for (int m = 0; m < NTOK; m++) if (m < n) {
            float e = expf(sc[m]-mx); sc[m] = e; ssum += e;
        }
        float gl = 0.f;
        #pragma unroll
        for (int m = 0; m < NTOK; m++) if (m < n)
            gl += sc[m]*ps[m*384 + 128 + tid];
        glim[tid] = gl/ssum;
    }
    __syncthreads();
    // glimpse @ W_out
    {
        float g = 0.f;
        for (int j = 0; j < Dm; j++) g += glim[j]*W_out[j*Dm + tid];
        go[tid] = g;
    }
    __syncthreads();
    // logits per token (one warp per token, strided)
    {
        int w = tid >> 5, lane = tid & 31;
        for (int t = w; t < n; t += 4) {
            float p = 0.f;
            #pragma unroll
            for (int r = 0; r < 4; r++)
                p += go[lane + 32*r]*ps[t*384 + 256 + lane + 32*r];
            #pragma unroll
            for (int o = 16; o > 0; o >>= 1) p += __shfl_xor_sync(0xffffffffu, p, o);
            if (lane == 0)
                logit_s[t] = tanhf(p * 0.08838834764831845f) * 10.f;
        }
    }
    __syncthreads();
    // log_softmax + argmax (first-max tie rule) on warp 0
    if (tid < 32) {
        float v = (tid < n) ? logit_s[tid] : -1e30f;
        float m = v;
        #pragma unroll
        for (int o = 16; o > 0; o >>= 1) m = fmaxf(m, __shfl_xor_sync(0xffffffffu, m, o));
        int idx = (tid < n && v == m) ? tid : (1 << 30);
        #pragma unroll
        for (int o = 16; o > 0; o >>= 1) idx = min(idx, __shfl_xor_sync(0xffffffffu, idx, o));
        float e = (tid < n) ? expf(v - m) : 0.f;
        float se = e;
        #pragma unroll
        for (int o = 16; o > 0; o >>= 1) se += __shfl_xor_sync(0xffffffffu, se, o);
        if (tid == 0) { sel_s = idx; lp_s = logit_s[idx] - m - logf(se); }
    }
    __syncthreads();
    int sel = sel_s;

    // value head: relu(g_mean @ Wc1[:128,:] + cph) @ Wc2
    {
        float part = 0.f;
        #pragma unroll
        for (int r = 0; r < 4; r++) {
            int j = tid + 128*r;
            float acc = g_cph[j];
            for (int k = 0; k < Dm; k++) acc += gms[k]*Wc1[k*HIDd + j];
            part += fmaxf(acc, 0.f)*Wc2[j];
        }
        red[tid] = part;
    }
    __syncthreads();
    for (int st = 64; st > 0; st >>= 1) {
        if (tid < st) red[tid] += red[tid+st];
        __syncthreads();
    }

    // outputs + state (thread 0)
    if (tid == 0) {
        float val = red[0] + bc2[0];
        float cx = g_crd[b*NTOK*2 + sel*2], cy = g_crd[b*NTOK*2 + sel*2 + 1];
        float ir = 0.f;
        if (i == 0) {
            g_first[2*b] = cx; g_first[2*b+1] = cy;
        } else {
            float dx = cx - g_prev[2*b], dy = cy - g_prev[2*b+1];
            ir = -sqrtf(dx*dx + dy*dy);
        }
        g_prev[2*b] = cx; g_prev[2*b+1] = cy;
        int node = g_nidx[b*NTOK + sel];
        g_tours[b*NTOK + i] = node;
        out[             b*NTOK + i] = lp_s;        // log_ps
        out[Bsz*NTOK   + b*NTOK + i] = ir;          // irs
        out[2*Bsz*NTOK + b*NTOK + i] = val;         // vals
        out[3*Bsz*NTOK + 2*Bsz + b*NTOK + i] = (float)node;  // tours
    }
    __syncthreads();

    // compaction (stable removal of sel)
    if (i < NTOK-1) {
        for (int t = sel; t < n-1; t++)
            g_x[(size_t)b*NTOK*Dm + t*Dm + tid] = g_x[(size_t)b*NTOK*Dm + (t+1)*Dm + tid];
        if (tid < 2)
            for (int t = sel; t < n-1; t++)
                g_crd[b*NTOK*2 + t*2 + tid] = g_crd[b*NTOK*2 + (t+1)*2 + tid];
        if (tid == 0)
            for (int t = sel; t < n-1; t++)
                g_nidx[b*NTOK + t] = g_nidx[b*NTOK + t+1];
    }
}

// ---------------- final: tour cost + reward_final ----------------
__global__ void k_final(const float* __restrict__ coords, float* __restrict__ out)
{
    int b = blockIdx.x*blockDim.x + threadIdx.x;
    if (b >= Bsz) return;
    const int* tb = g_tours + b*NTOK;
    const float* cb = coords + b*NTOK*2;
    float x0 = cb[tb[0]*2], y0 = cb[tb[0]*2 + 1];
    float px = x0, py = y0;
    float cost = 0.f;
    for (int t = 1; t < NTOK; t++) {
        float x = cb[tb[t]*2], y = cb[tb[t]*2 + 1];
        float dx = x - px, dy = y - py;
        cost += sqrtf(dx*dx + dy*dy);
        px = x; py = y;
    }
    {
        float dx = x0 - px, dy = y0 - py;
        cost += sqrtf(dx*dx + dy*dy);
    }
    out[3*Bsz*NTOK + b] = cost;                       // cost
    float fx = g_first[2*b] - g_prev[2*b];
    float fy = g_first[2*b+1] - g_prev[2*b+1];
    out[3*Bsz*NTOK + Bsz + b] = -sqrtf(fx*fx + fy*fy); // reward_final
}

// ---------------- host ----------------
extern "C" void kernel_launch(void* const* d_in, const int* in_sizes, int n_in,
                              void* d_out, int out_size)
{
    const float* coords  = (const float*)d_in[0];
    const float* Wi      = (const float*)d_in[1];
    const float* bi      = (const float*)d_in[2];
    const float* W_ph    = (const float*)d_in[3];
    const float* eWq     = (const float*)d_in[4];
    const float* eWk     = (const float*)d_in[5];
    const float* eWv     = (const float*)d_in[6];
    const float* eWo     = (const float*)d_in[7];
    const float* eg1     = (const float*)d_in[8];
    const float* eb1     = (const float*)d_in[9];
    const float* effW1   = (const float*)d_in[10];
    const float* effb1   = (const float*)d_in[11];
    const float* effW2   = (const float*)d_in[12];
    const float* effb2   = (const float*)d_in[13];
    const float* eg2     = (const float*)d_in[14];
    const float* eb2     = (const float*)d_in[15];
    const float* W_node  = (const float*)d_in[16];
    const float* W_fixed = (const float*)d_in[17];
    const float* W_step  = (const float*)d_in[18];
    const float* W_out   = (const float*)d_in[19];
    const float* Wc1     = (const float*)d_in[20];
    const float* bc1     = (const float*)d_in[21];
    const float* Wc2     = (const float*)d_in[22];
    const float* bc2     = (const float*)d_in[23];
    float* out = (float*)d_out;

    k_embed<<<Bsz, 128>>>(coords, Wi, bi);
    k_setup<<<1, 512>>>(W_ph, W_step, Wc1, bc1);

    for (int i = 0; i < NTOK; i++) {
        int n = NTOK - i;
        for (int l = 0; l < 3; l++) {
            k_mha<<<Bsz, 128>>>(l == 0 ? 0 : 1,
                                eWq + l*16384, eWk + l*16384,
                                eWv + l*16384, eWo + l*16384, n);
            k_bnred<<<Dm, 128>>>(1, eg1 + l*Dm, eb1 + l*Dm, n);
            k_ffn<<<Bsz, 128>>>(effW1 + l*Dm*FFd, effb1 + l*FFd,
                                effW2 + l*FFd*Dm, effb2 + l*Dm, n);
            k_bnred<<<Dm, 128>>>(2, eg2 + l*Dm, eb2 + l*Dm, n);
        }
        k_decode<<<Bsz, 128>>>(i, n, W_node, W_fixed, W_out, Wc1, Wc2, bc2, out);
    }
    k_final<<<2, 256>>>(coords, out);
}